// round 1
// baseline (speedup 1.0000x reference)
#include <cuda_runtime.h>

#define NN 50000
#define EE 800000

// ---------------- scratch (device globals; no allocation allowed) ----------------
__device__ __align__(16) float g_h0[(size_t)NN * 128];   // layer input features
__device__ __align__(16) float g_h1[(size_t)NN * 128];   // h = x@W (interleaved [N][32][4] for heads=4)
__device__ __align__(16) float g_asrc[NN * 4];
__device__ __align__(16) float g_adst[NN * 4];
__device__ int g_deg[NN];
__device__ int g_ptr[NN + 1];
__device__ int g_csr[EE + NN];
__device__ int g_is64;

// ---------------- CSR build ----------------
__global__ void detect_kernel(const int* __restrict__ e32) {
    // int64 data (values < 2^31) has every odd int32 slot == 0
    __shared__ int any;
    if (threadIdx.x == 0) any = 0;
    __syncthreads();
    int local = 0;
    for (int i = threadIdx.x; i < 4096; i += blockDim.x)
        if (e32[2 * i + 1] != 0) local = 1;
    if (local) any = 1;
    __syncthreads();
    if (threadIdx.x == 0) g_is64 = (any == 0) ? 1 : 0;
}

__global__ void init_deg_kernel() {
    int n = blockIdx.x * blockDim.x + threadIdx.x;
    if (n < NN) g_deg[n] = 1;   // self loop
}

__global__ void hist_kernel(const void* __restrict__ ei) {
    int e = blockIdx.x * blockDim.x + threadIdx.x;
    if (e >= EE) return;
    int d = g_is64 ? (int)((const long long*)ei)[EE + e]
                   : ((const int*)ei)[EE + e];
    atomicAdd(&g_deg[d], 1);
}

__global__ void scan_kernel() {
    __shared__ int wsum[32];
    __shared__ int s_carry;
    int t = threadIdx.x;
    if (t == 0) s_carry = 0;
    __syncthreads();
    for (int base = 0; base < NN; base += 1024) {
        int i = base + t;
        int v = (i < NN) ? g_deg[i] : 0;
        int x = v;
        #pragma unroll
        for (int off = 1; off < 32; off <<= 1) {
            int y = __shfl_up_sync(0xffffffffu, x, off);
            if ((t & 31) >= off) x += y;
        }
        if ((t & 31) == 31) wsum[t >> 5] = x;
        __syncthreads();
        if (t < 32) {
            int w = wsum[t];
            #pragma unroll
            for (int off = 1; off < 32; off <<= 1) {
                int y = __shfl_up_sync(0xffffffffu, w, off);
                if (t >= off) w += y;
            }
            wsum[t] = w;
        }
        __syncthreads();
        int incl = x + ((t >= 32) ? wsum[(t >> 5) - 1] : 0);
        int total = wsum[31];
        int carry = s_carry;
        if (i < NN) g_ptr[i] = carry + incl - v;   // exclusive
        __syncthreads();
        if (t == 0) s_carry = carry + total;
        __syncthreads();
    }
    if (t == 0) g_ptr[NN] = s_carry;
}

__global__ void init_csr_kernel() {
    int n = blockIdx.x * blockDim.x + threadIdx.x;
    if (n < NN) {
        g_csr[g_ptr[n]] = n;   // self loop at slot 0
        g_deg[n] = 1;          // reuse deg as scatter cursor
    }
}

__global__ void scatter_kernel(const void* __restrict__ ei) {
    int e = blockIdx.x * blockDim.x + threadIdx.x;
    if (e >= EE) return;
    int s, d;
    if (g_is64) {
        s = (int)((const long long*)ei)[e];
        d = (int)((const long long*)ei)[EE + e];
    } else {
        s = ((const int*)ei)[e];
        d = ((const int*)ei)[EE + e];
    }
    int pos = atomicAdd(&g_deg[d], 1);
    g_csr[g_ptr[d] + pos] = s;
}

// ---------------- fused GEMM + attention coefficients ----------------
// H = X[NN,128] @ W[128,M]; asrc[n,h] = dot(H[n,h,:], att_s[h,:]); same for adst.
// If ILV: H stored as [N][32][4] (channel-major, heads packed) for LDG.128 gathers.
template <int M, int HEADS, bool ILV>
__launch_bounds__(256)
__global__ void gemm_att_kernel(const float* __restrict__ X, const float* __restrict__ W,
                                const float* __restrict__ att_s, const float* __restrict__ att_d,
                                float* __restrict__ H, float* __restrict__ asrc,
                                float* __restrict__ adst) {
    constexpr int CG = M / 4;               // column groups (4 cols each)
    constexpr int RPT = (M == 128) ? 8 : 2; // rows per thread (block tile = 64 rows)
    constexpr int XS = 132;                 // padded SMEM row stride (floats)
    extern __shared__ float sh[];
    float* ws = sh;                 // 128 * M
    float* xs = sh + 128 * M;       // 64 * XS

    int t = threadIdx.x;
    int n0 = blockIdx.x * 64;

    for (int i = t; i < 128 * M / 4; i += 256)
        ((float4*)ws)[i] = ((const float4*)W)[i];
    for (int i = t; i < 64 * 32; i += 256) {
        int r = i >> 5, c = i & 31;
        int n = n0 + r;
        float4 v = make_float4(0.f, 0.f, 0.f, 0.f);
        if (n < NN) v = ((const float4*)X)[(size_t)n * 32 + c];
        *((float4*)(xs + r * XS + c * 4)) = v;
    }
    __syncthreads();

    int cg = t % CG;
    int rg = t / CG;
    int j0 = 4 * cg;

    float acc[RPT][4];
    #pragma unroll
    for (int r = 0; r < RPT; ++r) {
        acc[r][0] = 0.f; acc[r][1] = 0.f; acc[r][2] = 0.f; acc[r][3] = 0.f;
    }

    #pragma unroll 8
    for (int k = 0; k < 128; ++k) {
        float4 w4 = ((float4*)ws)[k * CG + cg];
        #pragma unroll
        for (int r = 0; r < RPT; ++r) {
            float xv = xs[(rg * RPT + r) * XS + k];
            acc[r][0] += xv * w4.x;
            acc[r][1] += xv * w4.y;
            acc[r][2] += xv * w4.z;
            acc[r][3] += xv * w4.w;
        }
    }

    // attention partial dots + 8-lane (one head) reduction
    int h = j0 >> 5;
    float4 as = ((const float4*)att_s)[cg];
    float4 ad = ((const float4*)att_d)[cg];
    #pragma unroll
    for (int r = 0; r < RPT; ++r) {
        int n = n0 + rg * RPT + r;
        float ps = acc[r][0] * as.x + acc[r][1] * as.y + acc[r][2] * as.z + acc[r][3] * as.w;
        float pd = acc[r][0] * ad.x + acc[r][1] * ad.y + acc[r][2] * ad.z + acc[r][3] * ad.w;
        #pragma unroll
        for (int off = 4; off >= 1; off >>= 1) {
            ps += __shfl_down_sync(0xffffffffu, ps, off, 8);
            pd += __shfl_down_sync(0xffffffffu, pd, off, 8);
        }
        if ((t & 7) == 0 && n < NN) {
            asrc[n * HEADS + h] = ps;
            adst[n * HEADS + h] = pd;
        }
    }

    // store H
    if (ILV) {
        #pragma unroll
        for (int r = 0; r < RPT; ++r) {
            int n = n0 + rg * RPT + r;
            if (n < NN) {
                #pragma unroll
                for (int i = 0; i < 4; ++i) {
                    int j = j0 + i;
                    int pos = ((j & 31) << 2) | (j >> 5);   // [c][h]
                    H[(size_t)n * 128 + pos] = acc[r][i];
                }
            }
        }
    } else {
        #pragma unroll
        for (int r = 0; r < RPT; ++r) {
            int n = n0 + rg * RPT + r;
            if (n < NN)
                ((float4*)H)[(size_t)n * CG + cg] =
                    make_float4(acc[r][0], acc[r][1], acc[r][2], acc[r][3]);
        }
    }
}

// ---------------- per-node softmax + aggregation (warp per node, no atomics) ----------------
__device__ __forceinline__ float lrelu(float v) { return fmaxf(v, 0.2f * v); }

template <int HEADS, int ACT>   // ACT: 0 = ELU, 1 = sigmoid
__launch_bounds__(256)
__global__ void agg_kernel(const float* __restrict__ feat,
                           const float* __restrict__ asrc, const float* __restrict__ adst,
                           const float* __restrict__ bias, float* __restrict__ out) {
    int n = (blockIdx.x * blockDim.x + threadIdx.x) >> 5;
    int lane = threadIdx.x & 31;
    if (n >= NN) return;
    int beg = g_ptr[n], end = g_ptr[n + 1];

    if (HEADS == 4) {
        float4 ad = ((const float4*)adst)[n];
        float m0 = -1e30f, m1 = -1e30f, m2 = -1e30f, m3 = -1e30f;
        for (int e = beg; e < end; ++e) {
            int s = g_csr[e];
            float4 a = ((const float4*)asrc)[s];
            m0 = fmaxf(m0, lrelu(a.x + ad.x));
            m1 = fmaxf(m1, lrelu(a.y + ad.y));
            m2 = fmaxf(m2, lrelu(a.z + ad.z));
            m3 = fmaxf(m3, lrelu(a.w + ad.w));
        }
        float a0 = 0.f, a1 = 0.f, a2 = 0.f, a3 = 0.f;
        float s0 = 0.f, s1 = 0.f, s2 = 0.f, s3 = 0.f;
        for (int e = beg; e < end; ++e) {
            int s = g_csr[e];
            float4 a = ((const float4*)asrc)[s];
            float w0 = __expf(lrelu(a.x + ad.x) - m0);
            float w1 = __expf(lrelu(a.y + ad.y) - m1);
            float w2 = __expf(lrelu(a.z + ad.z) - m2);
            float w3 = __expf(lrelu(a.w + ad.w) - m3);
            float4 v = ((const float4*)feat)[(size_t)s * 32 + lane];  // heads packed
            a0 += w0 * v.x; a1 += w1 * v.y; a2 += w2 * v.z; a3 += w3 * v.w;
            s0 += w0; s1 += w1; s2 += w2; s3 += w3;
        }
        float o0 = a0 / s0 + bias[lane];
        float o1 = a1 / s1 + bias[32 + lane];
        float o2 = a2 / s2 + bias[64 + lane];
        float o3 = a3 / s3 + bias[96 + lane];
        o0 = (o0 > 0.f) ? o0 : (__expf(o0) - 1.f);
        o1 = (o1 > 0.f) ? o1 : (__expf(o1) - 1.f);
        o2 = (o2 > 0.f) ? o2 : (__expf(o2) - 1.f);
        o3 = (o3 > 0.f) ? o3 : (__expf(o3) - 1.f);
        size_t b = (size_t)n * 128;
        out[b + lane] = o0;
        out[b + 32 + lane] = o1;
        out[b + 64 + lane] = o2;
        out[b + 96 + lane] = o3;
    } else {
        float ad = adst[n];
        float m = -1e30f;
        for (int e = beg; e < end; ++e) {
            int s = g_csr[e];
            m = fmaxf(m, lrelu(asrc[s] + ad));
        }
        float a = 0.f, ss = 0.f;
        for (int e = beg; e < end; ++e) {
            int s = g_csr[e];
            float w = __expf(lrelu(asrc[s] + ad) - m);
            a += w * feat[(size_t)s * 32 + lane];
            ss += w;
        }
        float o = a / ss + bias[lane];
        o = 1.f / (1.f + __expf(-o));
        out[(size_t)n * 32 + lane] = o;
    }
}

// ---------------- host launcher ----------------
extern "C" void kernel_launch(void* const* d_in, const int* in_sizes, int n_in,
                              void* d_out, int out_size) {
    const float* x = (const float*)d_in[0];
    const void* ei = d_in[1];
    const float* W[4]  = {(const float*)d_in[2], (const float*)d_in[6],
                          (const float*)d_in[10], (const float*)d_in[14]};
    const float* As[4] = {(const float*)d_in[3], (const float*)d_in[7],
                          (const float*)d_in[11], (const float*)d_in[15]};
    const float* Ad[4] = {(const float*)d_in[4], (const float*)d_in[8],
                          (const float*)d_in[12], (const float*)d_in[16]};
    const float* B[4]  = {(const float*)d_in[5], (const float*)d_in[9],
                          (const float*)d_in[13], (const float*)d_in[17]};
    float* out = (float*)d_out;

    float *p_h0, *p_h1, *p_asrc, *p_adst;
    cudaGetSymbolAddress((void**)&p_h0, g_h0);
    cudaGetSymbolAddress((void**)&p_h1, g_h1);
    cudaGetSymbolAddress((void**)&p_asrc, g_asrc);
    cudaGetSymbolAddress((void**)&p_adst, g_adst);

    constexpr int SMEM_BIG = (128 * 128 + 64 * 132) * 4;   // 99328 B
    constexpr int SMEM_SMALL = (128 * 32 + 64 * 132) * 4;  // 50176 B
    cudaFuncSetAttribute(gemm_att_kernel<128, 4, true>,
                         cudaFuncAttributeMaxDynamicSharedMemorySize, SMEM_BIG);
    cudaFuncSetAttribute(gemm_att_kernel<32, 1, false>,
                         cudaFuncAttributeMaxDynamicSharedMemorySize, SMEM_SMALL);

    // CSR build
    detect_kernel<<<1, 256>>>((const int*)ei);
    init_deg_kernel<<<(NN + 255) / 256, 256>>>();
    hist_kernel<<<(EE + 255) / 256, 256>>>(ei);
    scan_kernel<<<1, 1024>>>();
    init_csr_kernel<<<(NN + 255) / 256, 256>>>();
    scatter_kernel<<<(EE + 255) / 256, 256>>>(ei);

    const int GB = (NN + 63) / 64;            // 782
    const int AB = (NN * 32 + 255) / 256;     // 6250

    // layer 1
    gemm_att_kernel<128, 4, true><<<GB, 256, SMEM_BIG>>>(x, W[0], As[0], Ad[0],
                                                         p_h1, p_asrc, p_adst);
    agg_kernel<4, 0><<<AB, 256>>>(p_h1, p_asrc, p_adst, B[0], p_h0);
    // layer 2
    gemm_att_kernel<128, 4, true><<<GB, 256, SMEM_BIG>>>(p_h0, W[1], As[1], Ad[1],
                                                         p_h1, p_asrc, p_adst);
    agg_kernel<4, 0><<<AB, 256>>>(p_h1, p_asrc, p_adst, B[1], p_h0);
    // layer 3
    gemm_att_kernel<128, 4, true><<<GB, 256, SMEM_BIG>>>(p_h0, W[2], As[2], Ad[2],
                                                         p_h1, p_asrc, p_adst);
    agg_kernel<4, 0><<<AB, 256>>>(p_h1, p_asrc, p_adst, B[2], p_h0);
    // layer 4 (heads=1, 32 labels) -> sigmoid -> d_out
    gemm_att_kernel<32, 1, false><<<GB, 256, SMEM_SMALL>>>(p_h0, W[3], As[3], Ad[3],
                                                           p_h1, p_asrc, p_adst);
    agg_kernel<1, 1><<<AB, 256>>>(p_h1, p_asrc, p_adst, B[3], out);
}

// round 2
// speedup vs baseline: 1.4250x; 1.4250x over previous
#include <cuda_runtime.h>

#define NN 50000
#define EE 800000
#define NBS 49   // ceil(NN/1024)

typedef unsigned long long u64;

// ---------------- scratch (device globals; no allocation allowed) ----------------
__device__ __align__(16) float g_h0[(size_t)NN * 128];   // layer input features
__device__ __align__(16) float g_h1[(size_t)NN * 128];   // h = x@W (interleaved [N][32][4] for heads=4)
__device__ __align__(16) float g_asrc[NN * 4];
__device__ __align__(16) float g_adst[NN * 4];
__device__ int g_deg[NN];
__device__ int g_ptr[NN + 1];
__device__ int g_bsum[64];
__device__ int g_csr[EE + NN];
__device__ int g_is64;

// ---------------- f32x2 helpers ----------------
__device__ __forceinline__ u64 pack2(float x) {
    u64 r;
    asm("mov.b64 %0, {%1, %1};" : "=l"(r) : "f"(x));
    return r;
}
__device__ __forceinline__ void ffma2(u64& d, u64 a, u64 b) {
    asm("fma.rn.f32x2 %0, %1, %2, %0;" : "+l"(d) : "l"(a), "l"(b));
}
__device__ __forceinline__ void unpack2(u64 v, float& lo, float& hi) {
    asm("mov.b64 {%0, %1}, %2;" : "=f"(lo), "=f"(hi) : "l"(v));
}

// ---------------- CSR build ----------------
__global__ void detect_kernel(const int* __restrict__ e32) {
    __shared__ int any;
    if (threadIdx.x == 0) any = 0;
    __syncthreads();
    int local = 0;
    for (int i = threadIdx.x; i < 4096; i += blockDim.x)
        if (e32[2 * i + 1] != 0) local = 1;
    if (local) any = 1;
    __syncthreads();
    if (threadIdx.x == 0) g_is64 = (any == 0) ? 1 : 0;
}

__global__ void init_deg_kernel() {
    int n = blockIdx.x * blockDim.x + threadIdx.x;
    if (n < NN) g_deg[n] = 1;   // self loop
}

__global__ void hist_kernel(const void* __restrict__ ei) {
    int e = blockIdx.x * blockDim.x + threadIdx.x;
    if (e >= EE) return;
    int d = g_is64 ? (int)((const long long*)ei)[EE + e]
                   : ((const int*)ei)[EE + e];
    atomicAdd(&g_deg[d], 1);
}

// 3-phase exclusive scan of g_deg -> g_ptr
__global__ void scan_local_kernel() {
    __shared__ int wsum[32];
    int t = threadIdx.x;
    int i = blockIdx.x * 1024 + t;
    int v = (i < NN) ? g_deg[i] : 0;
    int x = v;
    #pragma unroll
    for (int off = 1; off < 32; off <<= 1) {
        int y = __shfl_up_sync(0xffffffffu, x, off);
        if ((t & 31) >= off) x += y;
    }
    if ((t & 31) == 31) wsum[t >> 5] = x;
    __syncthreads();
    if (t < 32) {
        int w = wsum[t];
        #pragma unroll
        for (int off = 1; off < 32; off <<= 1) {
            int y = __shfl_up_sync(0xffffffffu, w, off);
            if (t >= off) w += y;
        }
        wsum[t] = w;
    }
    __syncthreads();
    int incl = x + ((t >= 32) ? wsum[(t >> 5) - 1] : 0);
    if (i < NN) g_ptr[i] = incl - v;
    if (t == 1023) g_bsum[blockIdx.x] = incl;
}

__global__ void scan_block_kernel() {   // 1 warp
    int t = threadIdx.x;
    int carry = 0;
    for (int base = 0; base < NBS; base += 32) {
        int v = (base + t < NBS) ? g_bsum[base + t] : 0;
        int x = v;
        #pragma unroll
        for (int off = 1; off < 32; off <<= 1) {
            int y = __shfl_up_sync(0xffffffffu, x, off);
            if (t >= off) x += y;
        }
        if (base + t < NBS) g_bsum[base + t] = carry + x - v;
        carry += __shfl_sync(0xffffffffu, x, 31);
    }
    if (t == 0) g_ptr[NN] = carry;
}

__global__ void scan_add_kernel() {
    int i = blockIdx.x * 1024 + threadIdx.x;
    if (i < NN) g_ptr[i] += g_bsum[blockIdx.x];
}

__global__ void init_csr_kernel() {
    int n = blockIdx.x * blockDim.x + threadIdx.x;
    if (n < NN) {
        g_csr[g_ptr[n]] = n;   // self loop at slot 0
        g_deg[n] = 1;          // reuse deg as scatter cursor
    }
}

__global__ void scatter_kernel(const void* __restrict__ ei) {
    int e = blockIdx.x * blockDim.x + threadIdx.x;
    if (e >= EE) return;
    int s, d;
    if (g_is64) {
        s = (int)((const long long*)ei)[e];
        d = (int)((const long long*)ei)[EE + e];
    } else {
        s = ((const int*)ei)[e];
        d = ((const int*)ei)[EE + e];
    }
    int pos = atomicAdd(&g_deg[d], 1);
    g_csr[g_ptr[d] + pos] = s;
}

// ---------------- fused GEMM + attention coefficients (f32x2 packed FFMA) ----------------
template <int M, int HEADS, bool ILV>
__launch_bounds__(256)
__global__ void gemm_att_kernel(const float* __restrict__ X, const float* __restrict__ W,
                                const float* __restrict__ att_s, const float* __restrict__ att_d,
                                float* __restrict__ H, float* __restrict__ asrc,
                                float* __restrict__ adst) {
    constexpr int CG = M / 4;               // column groups (4 cols each)
    constexpr int RPT = (M == 128) ? 8 : 2; // rows per thread (block tile = 64 rows)
    constexpr int XS = 132;                 // padded SMEM row stride (floats)
    extern __shared__ float sh[];
    float* ws = sh;                 // 128 * M
    float* xs = sh + 128 * M;       // 64 * XS

    int t = threadIdx.x;
    int n0 = blockIdx.x * 64;

    for (int i = t; i < 128 * M / 4; i += 256)
        ((float4*)ws)[i] = ((const float4*)W)[i];
    for (int i = t; i < 64 * 32; i += 256) {
        int r = i >> 5, c = i & 31;
        int n = n0 + r;
        float4 v = make_float4(0.f, 0.f, 0.f, 0.f);
        if (n < NN) v = ((const float4*)X)[(size_t)n * 32 + c];
        *((float4*)(xs + r * XS + c * 4)) = v;
    }
    __syncthreads();

    int cg = t % CG;
    int rg = t / CG;
    int j0 = 4 * cg;

    u64 acc2[RPT][2];
    #pragma unroll
    for (int r = 0; r < RPT; ++r) { acc2[r][0] = 0ull; acc2[r][1] = 0ull; }

    const ulonglong2* wsp = (const ulonglong2*)ws;
    #pragma unroll 8
    for (int k = 0; k < 128; ++k) {
        ulonglong2 wp = wsp[k * CG + cg];   // {w0,w1},{w2,w3}
        #pragma unroll
        for (int r = 0; r < RPT; ++r) {
            u64 xp = pack2(xs[(rg * RPT + r) * XS + k]);
            ffma2(acc2[r][0], xp, wp.x);
            ffma2(acc2[r][1], xp, wp.y);
        }
    }

    float acc[RPT][4];
    #pragma unroll
    for (int r = 0; r < RPT; ++r) {
        unpack2(acc2[r][0], acc[r][0], acc[r][1]);
        unpack2(acc2[r][1], acc[r][2], acc[r][3]);
    }

    // attention partial dots + 8-lane (one head) reduction
    int h = j0 >> 5;
    float4 as = ((const float4*)att_s)[cg];
    float4 ad = ((const float4*)att_d)[cg];
    #pragma unroll
    for (int r = 0; r < RPT; ++r) {
        int n = n0 + rg * RPT + r;
        float ps = acc[r][0] * as.x + acc[r][1] * as.y + acc[r][2] * as.z + acc[r][3] * as.w;
        float pd = acc[r][0] * ad.x + acc[r][1] * ad.y + acc[r][2] * ad.z + acc[r][3] * ad.w;
        #pragma unroll
        for (int off = 4; off >= 1; off >>= 1) {
            ps += __shfl_down_sync(0xffffffffu, ps, off, 8);
            pd += __shfl_down_sync(0xffffffffu, pd, off, 8);
        }
        if ((t & 7) == 0 && n < NN) {
            asrc[n * HEADS + h] = ps;
            adst[n * HEADS + h] = pd;
        }
    }

    // store H
    if (ILV) {
        #pragma unroll
        for (int r = 0; r < RPT; ++r) {
            int n = n0 + rg * RPT + r;
            if (n < NN) {
                #pragma unroll
                for (int i = 0; i < 4; ++i) {
                    int j = j0 + i;
                    int pos = ((j & 31) << 2) | (j >> 5);   // [c][h]
                    H[(size_t)n * 128 + pos] = acc[r][i];
                }
            }
        }
    } else {
        #pragma unroll
        for (int r = 0; r < RPT; ++r) {
            int n = n0 + rg * RPT + r;
            if (n < NN)
                ((float4*)H)[(size_t)n * CG + cg] =
                    make_float4(acc[r][0], acc[r][1], acc[r][2], acc[r][3]);
        }
    }
}

// ---------------- per-node softmax + aggregation (warp per node, lane-parallel weights) ----------------
__device__ __forceinline__ float lrelu(float v) { return fmaxf(v, 0.2f * v); }

template <int HEADS, int ACT>   // ACT: 0 = ELU, 1 = sigmoid
__launch_bounds__(256)
__global__ void agg_kernel(const float* __restrict__ feat,
                           const float* __restrict__ asrc, const float* __restrict__ adst,
                           const float* __restrict__ bias, float* __restrict__ out) {
    __shared__ float4 s_w4[8][32];
    __shared__ int s_src[8][32];
    int wid = threadIdx.x >> 5;
    int lane = threadIdx.x & 31;
    int n = blockIdx.x * 8 + wid;
    if (n >= NN) return;
    int beg = g_ptr[n], end = g_ptr[n + 1];
    const float4* feat4 = (const float4*)feat;

    if (HEADS == 4) {
        float4 ad = ((const float4*)adst)[n];
        // pass 1: lane-parallel max over in-edges
        float m0 = -1e30f, m1 = -1e30f, m2 = -1e30f, m3 = -1e30f;
        for (int e = beg + lane; e < end; e += 32) {
            int s = g_csr[e];
            float4 a = ((const float4*)asrc)[s];
            m0 = fmaxf(m0, lrelu(a.x + ad.x));
            m1 = fmaxf(m1, lrelu(a.y + ad.y));
            m2 = fmaxf(m2, lrelu(a.z + ad.z));
            m3 = fmaxf(m3, lrelu(a.w + ad.w));
        }
        #pragma unroll
        for (int off = 16; off >= 1; off >>= 1) {
            m0 = fmaxf(m0, __shfl_xor_sync(0xffffffffu, m0, off));
            m1 = fmaxf(m1, __shfl_xor_sync(0xffffffffu, m1, off));
            m2 = fmaxf(m2, __shfl_xor_sync(0xffffffffu, m2, off));
            m3 = fmaxf(m3, __shfl_xor_sync(0xffffffffu, m3, off));
        }
        // pass 2: lane-parallel exp weights staged to smem, uniform aggregation
        float a0 = 0.f, a1 = 0.f, a2 = 0.f, a3 = 0.f;
        float s0 = 0.f, s1 = 0.f, s2 = 0.f, s3 = 0.f;
        for (int base = beg; base < end; base += 32) {
            int cnt = min(32, end - base);
            if (lane < cnt) {
                int s = g_csr[base + lane];
                float4 a = ((const float4*)asrc)[s];
                float4 wv;
                wv.x = __expf(lrelu(a.x + ad.x) - m0);
                wv.y = __expf(lrelu(a.y + ad.y) - m1);
                wv.z = __expf(lrelu(a.z + ad.z) - m2);
                wv.w = __expf(lrelu(a.w + ad.w) - m3);
                s_w4[wid][lane] = wv;
                s_src[wid][lane] = s;
                s0 += wv.x; s1 += wv.y; s2 += wv.z; s3 += wv.w;
            }
            __syncwarp();
            for (int i = 0; i < cnt; ++i) {
                float4 wv = s_w4[wid][i];
                int si = s_src[wid][i];
                float4 v = feat4[(size_t)si * 32 + lane];   // heads packed
                a0 += wv.x * v.x; a1 += wv.y * v.y; a2 += wv.z * v.z; a3 += wv.w * v.w;
            }
            __syncwarp();
        }
        #pragma unroll
        for (int off = 16; off >= 1; off >>= 1) {
            s0 += __shfl_xor_sync(0xffffffffu, s0, off);
            s1 += __shfl_xor_sync(0xffffffffu, s1, off);
            s2 += __shfl_xor_sync(0xffffffffu, s2, off);
            s3 += __shfl_xor_sync(0xffffffffu, s3, off);
        }
        float o0 = a0 / s0 + bias[lane];
        float o1 = a1 / s1 + bias[32 + lane];
        float o2 = a2 / s2 + bias[64 + lane];
        float o3 = a3 / s3 + bias[96 + lane];
        o0 = (o0 > 0.f) ? o0 : (__expf(o0) - 1.f);
        o1 = (o1 > 0.f) ? o1 : (__expf(o1) - 1.f);
        o2 = (o2 > 0.f) ? o2 : (__expf(o2) - 1.f);
        o3 = (o3 > 0.f) ? o3 : (__expf(o3) - 1.f);
        size_t b = (size_t)n * 128;
        out[b + lane] = o0;
        out[b + 32 + lane] = o1;
        out[b + 64 + lane] = o2;
        out[b + 96 + lane] = o3;
    } else {
        float* s_wf = (float*)&s_w4[wid][0];
        float ad = adst[n];
        float m = -1e30f;
        for (int e = beg + lane; e < end; e += 32)
            m = fmaxf(m, lrelu(asrc[g_csr[e]] + ad));
        #pragma unroll
        for (int off = 16; off >= 1; off >>= 1)
            m = fmaxf(m, __shfl_xor_sync(0xffffffffu, m, off));
        float acc = 0.f, ssum = 0.f;
        for (int base = beg; base < end; base += 32) {
            int cnt = min(32, end - base);
            if (lane < cnt) {
                int s = g_csr[base + lane];
                float wgt = __expf(lrelu(asrc[s] + ad) - m);
                s_wf[lane] = wgt;
                s_src[wid][lane] = s;
                ssum += wgt;
            }
            __syncwarp();
            for (int i = 0; i < cnt; ++i) {
                float wi = s_wf[i];
                int si = s_src[wid][i];
                acc += wi * feat[(size_t)si * 32 + lane];
            }
            __syncwarp();
        }
        #pragma unroll
        for (int off = 16; off >= 1; off >>= 1)
            ssum += __shfl_xor_sync(0xffffffffu, ssum, off);
        float o = acc / ssum + bias[lane];
        o = 1.f / (1.f + __expf(-o));
        out[(size_t)n * 32 + lane] = o;
    }
}

// ---------------- host launcher ----------------
extern "C" void kernel_launch(void* const* d_in, const int* in_sizes, int n_in,
                              void* d_out, int out_size) {
    const float* x = (const float*)d_in[0];
    const void* ei = d_in[1];
    const float* W[4]  = {(const float*)d_in[2], (const float*)d_in[6],
                          (const float*)d_in[10], (const float*)d_in[14]};
    const float* As[4] = {(const float*)d_in[3], (const float*)d_in[7],
                          (const float*)d_in[11], (const float*)d_in[15]};
    const float* Ad[4] = {(const float*)d_in[4], (const float*)d_in[8],
                          (const float*)d_in[12], (const float*)d_in[16]};
    const float* B[4]  = {(const float*)d_in[5], (const float*)d_in[9],
                          (const float*)d_in[13], (const float*)d_in[17]};
    float* out = (float*)d_out;

    float *p_h0, *p_h1, *p_asrc, *p_adst;
    cudaGetSymbolAddress((void**)&p_h0, g_h0);
    cudaGetSymbolAddress((void**)&p_h1, g_h1);
    cudaGetSymbolAddress((void**)&p_asrc, g_asrc);
    cudaGetSymbolAddress((void**)&p_adst, g_adst);

    constexpr int SMEM_BIG = (128 * 128 + 64 * 132) * 4;   // 99328 B
    constexpr int SMEM_SMALL = (128 * 32 + 64 * 132) * 4;  // 50176 B
    cudaFuncSetAttribute(gemm_att_kernel<128, 4, true>,
                         cudaFuncAttributeMaxDynamicSharedMemorySize, SMEM_BIG);
    cudaFuncSetAttribute(gemm_att_kernel<32, 1, false>,
                         cudaFuncAttributeMaxDynamicSharedMemorySize, SMEM_SMALL);

    // CSR build
    detect_kernel<<<1, 256>>>((const int*)ei);
    init_deg_kernel<<<(NN + 255) / 256, 256>>>();
    hist_kernel<<<(EE + 255) / 256, 256>>>(ei);
    scan_local_kernel<<<NBS, 1024>>>();
    scan_block_kernel<<<1, 32>>>();
    scan_add_kernel<<<NBS, 1024>>>();
    init_csr_kernel<<<(NN + 255) / 256, 256>>>();
    scatter_kernel<<<(EE + 255) / 256, 256>>>(ei);

    const int GB = (NN + 63) / 64;            // 782
    const int AB = (NN + 7) / 8;              // 6250 (8 warps/block)

    // layer 1
    gemm_att_kernel<128, 4, true><<<GB, 256, SMEM_BIG>>>(x, W[0], As[0], Ad[0],
                                                         p_h1, p_asrc, p_adst);
    agg_kernel<4, 0><<<AB, 256>>>(p_h1, p_asrc, p_adst, B[0], p_h0);
    // layer 2
    gemm_att_kernel<128, 4, true><<<GB, 256, SMEM_BIG>>>(p_h0, W[1], As[1], Ad[1],
                                                         p_h1, p_asrc, p_adst);
    agg_kernel<4, 0><<<AB, 256>>>(p_h1, p_asrc, p_adst, B[1], p_h0);
    // layer 3
    gemm_att_kernel<128, 4, true><<<GB, 256, SMEM_BIG>>>(p_h0, W[2], As[2], Ad[2],
                                                         p_h1, p_asrc, p_adst);
    agg_kernel<4, 0><<<AB, 256>>>(p_h1, p_asrc, p_adst, B[2], p_h0);
    // layer 4 (heads=1, 32 labels) -> sigmoid -> d_out
    gemm_att_kernel<32, 1, false><<<GB, 256, SMEM_SMALL>>>(p_h0, W[3], As[3], Ad[3],
                                                           p_h1, p_asrc, p_adst);
    agg_kernel<1, 1><<<AB, 256>>>(p_h1, p_asrc, p_adst, B[3], out);
}